// round 11
// baseline (speedup 1.0000x reference)
#include <cuda_runtime.h>
#include <math.h>

#define BATCH 8
#define NCLS 3
#define H 384
#define W 384
#define HW (H*W)
#define NBC 24
#define JT 8
#define NWARP 12   // 384/32
#define NWORD 12   // H/32 mask words per column
#define R 4        // rows per k2 block
#define RG (H/R)   // 96 row-groups
#define P 32       // fast-path EDT pad/radius
#define SENT2 1046529.0f   // 1023^2

// Scratch (device globals, fully overwritten each launch)
// layout: [b][c][word][j]
__device__ unsigned g_mask[BATCH*3*NWORD*W];
__device__ int      g_pn  [BATCH*3*NWORD*W];   // low16 = prev row (s16), high16 = next row (s16)
__device__ float g_psum_bg[NBC*RG];
__device__ float g_psum_fg[NBC*RG];
__device__ float g_pmax_bg[NBC*RG];
__device__ float g_pmax_fg[NBC*RG];

// ---------------------------------------------------------------------------
// k1: build per-column class bitmasks via ballot (thread = row, 8-col tile)
// and per (col,class,word) nearest-set-row below/above (prev/next, s16 pair).
// ---------------------------------------------------------------------------
__global__ void __launch_bounds__(384) k1_masks(const int* __restrict__ targets) {
    __shared__ unsigned sm[NWORD][24];   // [word][jj*3+c]
    const int i = threadIdx.x;           // row
    const int lane = i & 31, w = i >> 5;
    const int b = blockIdx.y;
    const int j0 = blockIdx.x * JT;

    const int4* tp = (const int4*)(targets + b*HW + i*W + j0);
    int4 ta = tp[0], tb = tp[1];         // two independent LDG.128
    int t[8] = {ta.x, ta.y, ta.z, ta.w, tb.x, tb.y, tb.z, tb.w};

    unsigned bal[24];
    #pragma unroll
    for (int jj = 0; jj < 8; jj++) {
        unsigned b0 = __ballot_sync(0xffffffffu, t[jj] == 0);
        unsigned b1 = __ballot_sync(0xffffffffu, t[jj] == 1);
        bal[jj*3+0] = b0;
        bal[jj*3+1] = b1;
        bal[jj*3+2] = ~(b0 | b1);
    }
    if (lane == 0) {
        #pragma unroll
        for (int c = 0; c < 3; c++) {
            uint4* gm = (uint4*)&g_mask[((b*3 + c)*NWORD + w)*W + j0];
            gm[0] = make_uint4(bal[0*3+c], bal[1*3+c], bal[2*3+c], bal[3*3+c]);
            gm[1] = make_uint4(bal[4*3+c], bal[5*3+c], bal[6*3+c], bal[7*3+c]);
        }
        uint4* sp = (uint4*)sm[w];
        #pragma unroll
        for (int q = 0; q < 6; q++)
            sp[q] = make_uint4(bal[q*4+0], bal[q*4+1], bal[q*4+2], bal[q*4+3]);
    }
    __syncthreads();

    if (threadIdx.x < 288) {   // one thread per (c, jj, word)
        const int tt = threadIdx.x;
        const int c = tt / 96, r96 = tt % 96;
        const int jj = r96 / NWORD, w2 = r96 % NWORD;
        const int s = jj*3 + c;
        int prev = -2000;
        for (int ww = w2 - 1; ww >= 0; --ww) {
            unsigned m = sm[ww][s];
            if (m) { prev = ww*32 + 31 - __clz(m); break; }
        }
        int next = 3000;
        for (int ww = w2 + 1; ww < NWORD; ++ww) {
            unsigned m = sm[ww][s];
            if (m) { next = ww*32 + __ffs(m) - 1; break; }
        }
        g_pn[((b*3 + c)*NWORD + w2)*W + j0 + jj] =
            (int)(((unsigned)(prev & 0xffff)) | ((unsigned)next << 16));
    }
}

// ---------------------------------------------------------------------------
// k2: single-barrier fused kernel with WARP-UNIFORM STATIC EDT TRIP COUNT.
// rmax = warp-max of g over all 12 (class,row) planes; a pixel can only
// improve while r < g (update needs r^2 < best <= g^2), so r = 1..rmax is a
// provably sufficient candidate superset. Loop body is branch-free
// independent fmin updates (no per-trip exit chain). Logits prefetched to
// registers before phase 1. Sentinel pads to r <= P; bounds-checked cold
// fallback beyond. MUFU-minimized epilogue; one block reduction.
// ---------------------------------------------------------------------------
__global__ void __launch_bounds__(384) k2_fused(const float* __restrict__ logits) {
    __shared__ float sh[3][R][W + 2*P];
    __shared__ float red[NWARP][12];
    const int j = threadIdx.x;
    const int rg = blockIdx.x, b = blockIdx.y;
    const int row0 = rg * R;
    const int w = row0 >> 5;          // rows of this block share one mask word
    const int lane = j & 31, wid = j >> 5;

    // prefetch logits (12 independent LDG; latency hidden under phase 1)
    float l0[R], l1[R], l2[R];
    #pragma unroll
    for (int ri = 0; ri < R; ri++) {
        const float* lp = logits + (b*3)*HW + (row0 + ri)*W + j;
        l0[ri] = lp[0]; l1[ri] = lp[HW]; l2[ri] = lp[2*HW];
    }

    // sentinel pads
    if (j < 2*P) {
        const int side = (j < P) ? j : (W + j);
        #pragma unroll
        for (int c = 0; c < 3; c++)
            #pragma unroll
            for (int ri = 0; ri < R; ri++)
                sh[c][ri][side] = SENT2;
    }

    const int mbase = ((b*3)*NWORD + w)*W + j;   // class stride = NWORD*W
    float bb[3][R];     // running best d^2, init g^2
    int gmax = 0;
    #pragma unroll
    for (int c = 0; c < 3; c++) {
        const unsigned mwc = g_mask[mbase + c*NWORD*W];
        const int pn = g_pn[mbase + c*NWORD*W];
        const int prv = (int)(short)(pn & 0xffff);
        const int nxt = pn >> 16;
        #pragma unroll
        for (int ri = 0; ri < R; ri++) {
            const int row = row0 + ri;
            const int lr = row & 31;
            const unsigned lowmask = 0xffffffffu >> (31 - lr);
            const unsigned himask  = 0xffffffffu << lr;
            unsigned mlo = mwc & lowmask;
            int dfw = mlo ? (lr + __clz(mlo) - 31) : (row - prv);
            unsigned mhi = mwc & himask;
            int dbw = mhi ? (__ffs(mhi) - 1 - lr) : (nxt - row);
            int g = min(min(dfw, dbw), 1023);
            gmax = max(gmax, g);
            bb[c][ri] = (float)(g * g);
            sh[c][ri][P + j] = bb[c][ri];
        }
    }
    // warp-uniform sufficient radius (pixel j,c needs only r < g_c[j] <= rmax)
    const int rmax = (int)__reduce_max_sync(0xffffffffu, (unsigned)gmax);
    __syncthreads();   // the only block barrier before the reduction

    // EDT: static trip count, branch-free body (independent fmin updates)
    const int rfast = min(rmax, P);
    for (int r = 1; r <= rfast; r++) {
        const float rr = (float)(r * r);
        #pragma unroll
        for (int c = 0; c < 3; c++)
            #pragma unroll
            for (int ri = 0; ri < R; ri++)
                bb[c][ri] = fminf(bb[c][ri],
                                  fminf(sh[c][ri][P + j - r], sh[c][ri][P + j + r]) + rr);
    }
    // cold exact fallback (rmax > P: a class locally absent; bounds-checked)
    for (int r = P + 1; r <= rmax && r < W; r++) {
        const float rr = (float)(r * r);
        const int lo = j - r, hi = j + r;
        #pragma unroll
        for (int c = 0; c < 3; c++)
            #pragma unroll
            for (int ri = 0; ri < R; ri++) {
                float v = bb[c][ri];
                if (lo >= 0) v = fminf(v, sh[c][ri][P + lo] + rr);
                if (hi < W)  v = fminf(v, sh[c][ri][P + hi] + rr);
                bb[c][ri] = v;
            }
    }

    float accs[6] = {0,0,0,0,0,0};      // p*dbg, p*dfg per class
    float accm[6] = {0,0,0,0,0,0};      // max d2 bg, max d2 fg per class

    #pragma unroll
    for (int ri = 0; ri < R; ri++) {
        const float b0 = bb[0][ri], b1 = bb[1][ri], b2 = bb[2][ri];
        // bg sqrts once; fg sqrts = mins of bg sqrts (sqrt monotone)
        float sb0 = sqrtf(b0), sb1 = sqrtf(b1), sb2 = sqrtf(b2);
        float sf0 = fminf(sb1, sb2);
        float sf1 = fminf(sb0, sb2);
        float sf2 = fminf(sb0, sb1);

        // softmax normalized by class 2: e2 = 1 (identical values, 2 MUFU)
        float e0 = __expf(l0[ri] - l2[ri]), e1 = __expf(l1[ri] - l2[ri]);
        float inv = __fdividef(1.0f, e0 + e1 + 1.0f);
        float p0 = e0*inv, p1 = e1*inv, p2 = inv;

        accs[0] += p0 * sb0;
        accs[1] += p1 * sb1;
        accs[2] += p2 * sb2;
        accs[3] += p0 * sf0;
        accs[4] += p1 * sf1;
        accs[5] += p2 * sf2;
        accm[0] = fmaxf(accm[0], b0);
        accm[1] = fmaxf(accm[1], b1);
        accm[2] = fmaxf(accm[2], b2);
        accm[3] = fmaxf(accm[3], fminf(b1, b2));
        accm[4] = fmaxf(accm[4], fminf(b0, b2));
        accm[5] = fmaxf(accm[5], fminf(b0, b1));
    }

    // warp reduce: 6 sums via shuffles, 6 maxes via redux on positive bits
    #pragma unroll
    for (int off = 16; off; off >>= 1) {
        #pragma unroll
        for (int s = 0; s < 6; s++) accs[s] += __shfl_xor_sync(0xffffffffu, accs[s], off);
    }
    #pragma unroll
    for (int s = 0; s < 6; s++)
        accm[s] = __uint_as_float(__reduce_max_sync(0xffffffffu, __float_as_uint(accm[s])));

    if (lane == 0) {
        #pragma unroll
        for (int s = 0; s < 6; s++) { red[wid][s] = accs[s]; red[wid][6+s] = accm[s]; }
    }
    __syncthreads();
    if (threadIdx.x < 12) {
        int s = threadIdx.x;
        float acc = red[0][s];
        #pragma unroll
        for (int ww = 1; ww < NWARP; ww++)
            acc = (s < 6) ? (acc + red[ww][s]) : fmaxf(acc, red[ww][s]);
        int c = s % 3;
        int idx = (b*3 + c) * RG + rg;
        int grp = s / 3;
        if      (grp == 0) g_psum_bg[idx] = acc;
        else if (grp == 1) g_psum_fg[idx] = acc;
        else if (grp == 2) g_pmax_bg[idx] = sqrtf(acc);   // sqrt(max d2) == max d
        else               g_pmax_fg[idx] = sqrtf(acc);
    }
}

// ---------------------------------------------------------------------------
// k3: final reduce. Warp per (b,c) map; gate = (Mbg < 600) <=> mask nonempty.
// ---------------------------------------------------------------------------
__global__ void k3_final(float* out) {
    const int lane = threadIdx.x & 31, bc = threadIdx.x >> 5;   // 24 warps
    double sbg = 0.0, sfg = 0.0;
    float mbg = 0.0f, mfg = 0.0f;
    for (int r = lane; r < RG; r += 32) {
        sbg += (double)g_psum_bg[bc*RG + r];
        sfg += (double)g_psum_fg[bc*RG + r];
        mbg = fmaxf(mbg, g_pmax_bg[bc*RG + r]);
        mfg = fmaxf(mfg, g_pmax_fg[bc*RG + r]);
    }
    #pragma unroll
    for (int off = 16; off; off >>= 1) {
        sbg += __shfl_xor_sync(0xffffffffu, sbg, off);
        sfg += __shfl_xor_sync(0xffffffffu, sfg, off);
        mbg = fmaxf(mbg, __shfl_xor_sync(0xffffffffu, mbg, off));
        mfg = fmaxf(mfg, __shfl_xor_sync(0xffffffffu, mfg, off));
    }
    __shared__ double cs[24];
    if (lane == 0) {
        double contrib = 0.0;
        if (mbg < 600.0f) {   // mask nonempty (empty-map sentinel d >= 1023)
            contrib = sbg / (double)fmaxf(mbg, 1e-12f)
                    - sfg / (double)fmaxf(mfg, 1e-12f);
        }
        cs[bc] = contrib;
    }
    __syncthreads();
    if (threadIdx.x == 0) {
        double s = 0.0;
        #pragma unroll
        for (int k = 0; k < 24; k++) s += cs[k];
        out[0] = (float)(s / (24.0 * (double)HW));
    }
}

extern "C" void kernel_launch(void* const* d_in, const int* in_sizes, int n_in,
                              void* d_out, int out_size) {
    const float* logits  = (const float*)d_in[0];
    const int*   targets = (const int*)d_in[1];

    dim3 g1(W / JT, BATCH);
    k1_masks<<<g1, H>>>(targets);
    dim3 g2(RG, BATCH);
    k2_fused<<<g2, W>>>(logits);
    k3_final<<<1, 24 * 32>>>((float*)d_out);
}

// round 13
// speedup vs baseline: 1.1231x; 1.1231x over previous
#include <cuda_runtime.h>
#include <math.h>

#define BATCH 8
#define NCLS 3
#define H 384
#define W 384
#define HW (H*W)
#define NBC 24
#define NWARP 12   // 384/32
#define NWORD 12   // H/32 mask words per column
#define CT 16      // columns per k1 block
#define R 4        // rows per k2 block
#define RG (H/R)   // 96 row-groups
#define P 32       // fast-path EDT pad/radius
#define SENT2 1046529.0f   // 1023^2

// Scratch (device globals, fully overwritten each launch)
// layout: [b][c][word][j]
__device__ unsigned g_mask[BATCH*3*NWORD*W];
__device__ int      g_pn  [BATCH*3*NWORD*W];   // low16 = prev row (s16), high16 = next row (s16)
__device__ float g_psum_bg[NBC*RG];
__device__ float g_psum_fg[NBC*RG];
__device__ float g_pmax_bg[NBC*RG];
__device__ float g_pmax_fg[NBC*RG];

// ---------------------------------------------------------------------------
// k1: coalesced-load mask builder. Block = (16-col strip, batch), 512 threads.
// Phase A: each thread prefetches its 12 strip values (row-coalesced LDG,
// MLP=12) and stores to pad-17 smem. Phase B: warp <-> column; lane = row
// within word; ballots -> mask smem. Phase C: 576 work items (grid-stride
// over 512 threads!) write g_mask coalesced and scan words for prev/next.
// ---------------------------------------------------------------------------
__global__ void __launch_bounds__(512) k1_masks(const int* __restrict__ targets) {
    __shared__ int staged[H][CT + 1];          // pad 17: conflict-free both phases
    __shared__ unsigned msm[3][NWORD][CT];
    const int tid = threadIdx.x;
    const int b = blockIdx.y;
    const int j0 = blockIdx.x * CT;

    // Phase A: prefetch (coalesced within each row) then stage
    const int r = tid >> 4;        // 0..31 row-within-word
    const int c = tid & 15;        // 0..15 column
    int v[NWORD];
    #pragma unroll
    for (int w = 0; w < NWORD; w++)
        v[w] = targets[b*HW + (w*32 + r)*W + j0 + c];
    #pragma unroll
    for (int w = 0; w < NWORD; w++)
        staged[w*32 + r][c] = v[w];
    __syncthreads();

    // Phase B: ballots. warp ww <-> column ww, lane = row within word.
    const int ww = tid >> 5, lane = tid & 31;   // 16 warps
    #pragma unroll
    for (int w = 0; w < NWORD; w++) {
        int tv = staged[w*32 + lane][ww];
        unsigned b0 = __ballot_sync(0xffffffffu, tv == 0);
        unsigned b1 = __ballot_sync(0xffffffffu, tv == 1);
        if (lane == 0) {
            msm[0][w][ww] = b0;
            msm[1][w][ww] = b1;
            msm[2][w][ww] = ~(b0 | b1);
        }
    }
    __syncthreads();

    // Phase C: 576 items on 512 threads (grid-stride) — ALL items covered
    for (int t = tid; t < 3*NWORD*CT; t += 512) {
        const int c2  = t / (NWORD*CT);
        const int rem = t % (NWORD*CT);
        const int w2  = rem / CT;
        const int col = rem % CT;
        const int gidx = ((b*3 + c2)*NWORD + w2)*W + j0 + col;
        g_mask[gidx] = msm[c2][w2][col];
        int prev = -2000;
        for (int k = w2 - 1; k >= 0; --k) {
            unsigned m = msm[c2][k][col];
            if (m) { prev = k*32 + 31 - __clz(m); break; }
        }
        int next = 3000;
        for (int k = w2 + 1; k < NWORD; ++k) {
            unsigned m = msm[c2][k][col];
            if (m) { next = k*32 + __ffs(m) - 1; break; }
        }
        g_pn[gidx] = (int)(((unsigned)(prev & 0xffff)) | ((unsigned)next << 16));
    }
}

// ---------------------------------------------------------------------------
// k2: single-barrier fused kernel (round-10 structure, proven). Phase 1:
// derive all 12 g^2 (3 classes x 4 rows sharing one mask word) into padded
// row-major smem. One __syncthreads. Phase 2: per-row EDT with per-pixel
// exit, 2 radii per trip (extra updates are monotone no-ops), sentinel pads
// to r <= P, bounds-checked cold fallback. MUFU-minimized epilogue.
// ---------------------------------------------------------------------------
__global__ void __launch_bounds__(384) k2_fused(const float* __restrict__ logits) {
    __shared__ float sh[3][R][W + 2*P];
    __shared__ float red[NWARP][12];
    const int j = threadIdx.x;
    const int rg = blockIdx.x, b = blockIdx.y;
    const int row0 = rg * R;
    const int w = row0 >> 5;          // rows of this block share one mask word
    const int lane = j & 31, wid = j >> 5;

    // sentinel pads
    if (j < 2*P) {
        const int side = (j < P) ? j : (W + j);
        #pragma unroll
        for (int c = 0; c < 3; c++)
            #pragma unroll
            for (int ri = 0; ri < R; ri++)
                sh[c][ri][side] = SENT2;
    }

    const int mbase = ((b*3)*NWORD + w)*W + j;   // class stride = NWORD*W
    unsigned mw[3];
    int prv[3], nxt[3];
    #pragma unroll
    for (int c = 0; c < 3; c++) {
        mw[c] = g_mask[mbase + c*NWORD*W];
        int pn = g_pn[mbase + c*NWORD*W];
        prv[c] = (int)(short)(pn & 0xffff);
        nxt[c] = pn >> 16;
    }

    // phase 1: all column distances -> smem
    #pragma unroll
    for (int ri = 0; ri < R; ri++) {
        const int row = row0 + ri;
        const int lr = row & 31;                         // uniform
        const unsigned lowmask = 0xffffffffu >> (31 - lr);
        const unsigned himask  = 0xffffffffu << lr;
        #pragma unroll
        for (int c = 0; c < 3; c++) {
            unsigned mlo = mw[c] & lowmask;
            int dfw = mlo ? (lr + __clz(mlo) - 31) : (row - prv[c]);
            unsigned mhi = mw[c] & himask;
            int dbw = mhi ? (__ffs(mhi) - 1 - lr) : (nxt[c] - row);
            int g = min(min(dfw, dbw), 1023);
            sh[c][ri][P + j] = (float)(g * g);
        }
    }
    __syncthreads();   // the only block barrier before the reduction

    float accs[6] = {0,0,0,0,0,0};      // p*dbg, p*dfg per class
    float accm[6] = {0,0,0,0,0,0};      // max d2 bg, max d2 fg per class

    #pragma unroll
    for (int ri = 0; ri < R; ri++) {
        const int row = row0 + ri;
        const float* s0 = &sh[0][ri][P];
        const float* s1 = &sh[1][ri][P];
        const float* s2 = &sh[2][ri][P];
        float b0 = s0[j], b1 = s1[j], b2 = s2[j];
        float bestmax = fmaxf(b0, fmaxf(b1, b2));
        float rf = 1.0f;
        int r = 1;
        // fast path: 2 radii per trip (extra updates exact no-ops);
        // pads absorb out-of-range reads up to r+1 <= P
        while (rf*rf < bestmax && r + 1 <= P) {
            const float rr1 = rf*rf;
            const float rr2 = (rf + 1.0f)*(rf + 1.0f);
            b0 = fminf(b0, fminf(s0[j-r],   s0[j+r])   + rr1);
            b1 = fminf(b1, fminf(s1[j-r],   s1[j+r])   + rr1);
            b2 = fminf(b2, fminf(s2[j-r],   s2[j+r])   + rr1);
            b0 = fminf(b0, fminf(s0[j-r-1], s0[j+r+1]) + rr2);
            b1 = fminf(b1, fminf(s1[j-r-1], s1[j+r+1]) + rr2);
            b2 = fminf(b2, fminf(s2[j-r-1], s2[j+r+1]) + rr2);
            bestmax = fmaxf(b0, fmaxf(b1, b2));
            r += 2; rf += 2.0f;
        }
        // exact cold fallback (r > P; only when a class is locally absent)
        while (rf*rf < bestmax && r < W) {
            const float rr = rf*rf;
            const int lo = j - r, hi = j + r;
            if (lo >= 0) {
                b0 = fminf(b0, s0[lo] + rr);
                b1 = fminf(b1, s1[lo] + rr);
                b2 = fminf(b2, s2[lo] + rr);
            }
            if (hi < W) {
                b0 = fminf(b0, s0[hi] + rr);
                b1 = fminf(b1, s1[hi] + rr);
                b2 = fminf(b2, s2[hi] + rr);
            }
            bestmax = fmaxf(b0, fmaxf(b1, b2));
            r++; rf += 1.0f;
        }
        // bg sqrts once; fg sqrts = mins of bg sqrts (sqrt monotone)
        float sb0 = sqrtf(b0), sb1 = sqrtf(b1), sb2 = sqrtf(b2);
        float sf0 = fminf(sb1, sb2);
        float sf1 = fminf(sb0, sb2);
        float sf2 = fminf(sb0, sb1);

        // softmax normalized by class 2: e2 = 1 (identical values, 2 MUFU)
        const float* lp = logits + (b*3)*HW + row*W + j;
        float l2v = lp[2*HW];
        float e0 = __expf(lp[0] - l2v), e1 = __expf(lp[HW] - l2v);
        float inv = __fdividef(1.0f, e0 + e1 + 1.0f);
        float p0 = e0*inv, p1 = e1*inv, p2 = inv;

        accs[0] += p0 * sb0;
        accs[1] += p1 * sb1;
        accs[2] += p2 * sb2;
        accs[3] += p0 * sf0;
        accs[4] += p1 * sf1;
        accs[5] += p2 * sf2;
        accm[0] = fmaxf(accm[0], b0);
        accm[1] = fmaxf(accm[1], b1);
        accm[2] = fmaxf(accm[2], b2);
        accm[3] = fmaxf(accm[3], fminf(b1, b2));
        accm[4] = fmaxf(accm[4], fminf(b0, b2));
        accm[5] = fmaxf(accm[5], fminf(b0, b1));
    }

    // warp reduce: 6 sums via shuffles, 6 maxes via redux on positive bits
    #pragma unroll
    for (int off = 16; off; off >>= 1) {
        #pragma unroll
        for (int s = 0; s < 6; s++) accs[s] += __shfl_xor_sync(0xffffffffu, accs[s], off);
    }
    #pragma unroll
    for (int s = 0; s < 6; s++)
        accm[s] = __uint_as_float(__reduce_max_sync(0xffffffffu, __float_as_uint(accm[s])));

    if (lane == 0) {
        #pragma unroll
        for (int s = 0; s < 6; s++) { red[wid][s] = accs[s]; red[wid][6+s] = accm[s]; }
    }
    __syncthreads();
    if (threadIdx.x < 12) {
        int s = threadIdx.x;
        float acc = red[0][s];
        #pragma unroll
        for (int ww = 1; ww < NWARP; ww++)
            acc = (s < 6) ? (acc + red[ww][s]) : fmaxf(acc, red[ww][s]);
        int c = s % 3;
        int idx = (b*3 + c) * RG + rg;
        int grp = s / 3;
        if      (grp == 0) g_psum_bg[idx] = acc;
        else if (grp == 1) g_psum_fg[idx] = acc;
        else if (grp == 2) g_pmax_bg[idx] = sqrtf(acc);   // sqrt(max d2) == max d
        else               g_pmax_fg[idx] = sqrtf(acc);
    }
}

// ---------------------------------------------------------------------------
// k3: final reduce. Warp per (b,c) map; gate = (Mbg < 600) <=> mask nonempty.
// ---------------------------------------------------------------------------
__global__ void k3_final(float* out) {
    const int lane = threadIdx.x & 31, bc = threadIdx.x >> 5;   // 24 warps
    double sbg = 0.0, sfg = 0.0;
    float mbg = 0.0f, mfg = 0.0f;
    for (int r = lane; r < RG; r += 32) {
        sbg += (double)g_psum_bg[bc*RG + r];
        sfg += (double)g_psum_fg[bc*RG + r];
        mbg = fmaxf(mbg, g_pmax_bg[bc*RG + r]);
        mfg = fmaxf(mfg, g_pmax_fg[bc*RG + r]);
    }
    #pragma unroll
    for (int off = 16; off; off >>= 1) {
        sbg += __shfl_xor_sync(0xffffffffu, sbg, off);
        sfg += __shfl_xor_sync(0xffffffffu, sfg, off);
        mbg = fmaxf(mbg, __shfl_xor_sync(0xffffffffu, mbg, off));
        mfg = fmaxf(mfg, __shfl_xor_sync(0xffffffffu, mfg, off));
    }
    __shared__ double cs[24];
    if (lane == 0) {
        double contrib = 0.0;
        if (mbg < 600.0f) {   // mask nonempty (empty-map sentinel d >= 1023)
            contrib = sbg / (double)fmaxf(mbg, 1e-12f)
                    - sfg / (double)fmaxf(mfg, 1e-12f);
        }
        cs[bc] = contrib;
    }
    __syncthreads();
    if (threadIdx.x == 0) {
        double s = 0.0;
        #pragma unroll
        for (int k = 0; k < 24; k++) s += cs[k];
        out[0] = (float)(s / (24.0 * (double)HW));
    }
}

extern "C" void kernel_launch(void* const* d_in, const int* in_sizes, int n_in,
                              void* d_out, int out_size) {
    const float* logits  = (const float*)d_in[0];
    const int*   targets = (const int*)d_in[1];

    dim3 g1(W / CT, BATCH);
    k1_masks<<<g1, 512>>>(targets);
    dim3 g2(RG, BATCH);
    k2_fused<<<g2, W>>>(logits);
    k3_final<<<1, 24 * 32>>>((float*)d_out);
}